// round 1
// baseline (speedup 1.0000x reference)
#include <cuda_runtime.h>

#define LSEQ 512
#define UDIM 512
#define BDIM 4
#define HDIM 8
#define DDIM 64
#define HBDIM 32   // HDIM * BDIM

// ---------------- scratch (device globals, no allocation) ----------------
__device__ float g_Q[BDIM * LSEQ * UDIM];   // relu(queries@Wq+bq), [B*L, U]
__device__ float g_K[BDIM * LSEQ * UDIM];
__device__ float g_V[BDIM * LSEQ * UDIM];
__device__ float g_qm[BDIM * LSEQ];         // sign(|sum_u queries|) per (b,l)

// ---------------- kernel 1: fused GEMM + bias + relu ----------------
// out[m,n] = relu(sum_k X[m,k]*W[k,n] + b[n]);  X: [2048,512], W: [512,512]
// blockIdx.z selects Q/K/V problem. 64x64 tile, k-tile 32, 256 thr, 4x4/thread.
__global__ void qkv_gemm_kernel(const float* __restrict__ q_in,
                                const float* __restrict__ k_in,
                                const float* __restrict__ v_in,
                                const float* __restrict__ Wq, const float* __restrict__ bq,
                                const float* __restrict__ Wk, const float* __restrict__ bk,
                                const float* __restrict__ Wv, const float* __restrict__ bv) {
    const float* X; const float* W; const float* bias; float* dst;
    if (blockIdx.z == 0)      { X = q_in; W = Wq; bias = bq; dst = g_Q; }
    else if (blockIdx.z == 1) { X = k_in; W = Wk; bias = bk; dst = g_K; }
    else                      { X = v_in; W = Wv; bias = bv; dst = g_V; }

    __shared__ float Xs[64][32];
    __shared__ float Ws[32][64];

    const int tid = threadIdx.x;
    const int m0 = blockIdx.x * 64;
    const int n0 = blockIdx.y * 64;
    const int oty = tid >> 4;      // 0..15 -> 4 rows each
    const int otx = tid & 15;      // 0..15 -> 4 cols each

    float acc[4][4] = {};

    for (int kt = 0; kt < UDIM; kt += 32) {
        // X tile 64x32 = 512 float4 loads, 2 per thread
        #pragma unroll
        for (int i = 0; i < 2; i++) {
            int lin = tid + i * 256;          // 0..511
            int r = lin >> 3, c4 = lin & 7;
            float4 v = *(const float4*)(X + (size_t)(m0 + r) * UDIM + kt + c4 * 4);
            *(float4*)(&Xs[r][c4 * 4]) = v;
        }
        // W tile 32x64
        #pragma unroll
        for (int i = 0; i < 2; i++) {
            int lin = tid + i * 256;
            int r = lin >> 4, c4 = lin & 15;
            float4 v = *(const float4*)(W + (size_t)(kt + r) * UDIM + n0 + c4 * 4);
            *(float4*)(&Ws[r][c4 * 4]) = v;
        }
        __syncthreads();
        #pragma unroll
        for (int kk = 0; kk < 32; kk++) {
            float a[4], w[4];
            #pragma unroll
            for (int i = 0; i < 4; i++) a[i] = Xs[oty * 4 + i][kk];   // 2 rows/warp -> broadcast
            #pragma unroll
            for (int j = 0; j < 4; j++) w[j] = Ws[kk][otx * 4 + j];   // consecutive -> no conflict
            #pragma unroll
            for (int i = 0; i < 4; i++)
                #pragma unroll
                for (int j = 0; j < 4; j++) acc[i][j] += a[i] * w[j];
        }
        __syncthreads();
    }

    #pragma unroll
    for (int i = 0; i < 4; i++) {
        int m = m0 + oty * 4 + i;
        float4 o;
        #pragma unroll
        for (int j = 0; j < 4; j++) {
            float v = acc[i][j] + bias[n0 + otx * 4 + j];
            ((float*)&o)[j] = v > 0.f ? v : 0.f;
        }
        *(float4*)(dst + (size_t)m * UDIM + n0 + otx * 4) = o;
    }
}

// ---------------- kernel 2: query mask ----------------
// qm[row] = (sum_u queries[row,u] != 0) ? 1 : 0   (sign(|x|))
__global__ void qm_kernel(const float* __restrict__ q_in) {
    int warp = (blockIdx.x * blockDim.x + threadIdx.x) >> 5;
    int lane = threadIdx.x & 31;
    if (warp >= BDIM * LSEQ) return;
    float s = 0.f;
    for (int e = lane; e < UDIM; e += 32) s += q_in[(size_t)warp * UDIM + e];
    #pragma unroll
    for (int o = 16; o; o >>= 1) s += __shfl_xor_sync(0xffffffffu, s, o);
    if (lane == 0) g_qm[warp] = (s != 0.f) ? 1.f : 0.f;
}

// ---------------- kernel 3: fused euclidean attention ----------------
// Block = (64 q-rows, one hb). Flash-style over 16 k-tiles of 32.
// Writes attn_score (= raw score * qm) as it goes; online softmax for out.
__global__ void attn_kernel(float* __restrict__ out, float* __restrict__ score_out) {
    const int q0 = blockIdx.x * 64;
    const int hb = blockIdx.y;
    const int h = hb / BDIM;
    const int b = hb % BDIM;
    const float* Qg = g_Q + (size_t)(b * LSEQ) * UDIM + h * DDIM;
    const float* Kg = g_K + (size_t)(b * LSEQ) * UDIM + h * DDIM;
    const float* Vg = g_V + (size_t)(b * LSEQ) * UDIM + h * DDIM;

    __shared__ float Qs[64][68];    // Q tile [r][d], padded
    __shared__ float As[32][68];    // K tile then V tile [k][d], padded
    __shared__ float Ss[64][33];    // score / prob tile [r][k], padded
    __shared__ float qq_s[64], m_s[64], l_s[64], fac_s[64], kk_s[32], qm_s[64];

    const int tid = threadIdx.x;

    // load Q tile (64x64 = 1024 float4, 4/thread)
    #pragma unroll
    for (int i = 0; i < 4; i++) {
        int lin = tid + i * 256;
        int r = lin >> 4, c4 = lin & 15;
        float4 v = *(const float4*)(Qg + (size_t)(q0 + r) * UDIM + c4 * 4);
        *(float4*)(&Qs[r][c4 * 4]) = v;
    }
    if (tid < 64) {
        qm_s[tid] = g_qm[b * LSEQ + q0 + tid];
        m_s[tid] = -3.0e38f;
        l_s[tid] = 0.f;
    }
    __syncthreads();

    // qq norms: 4 threads per row
    {
        int r = tid >> 2, part = tid & 3;
        float s = 0.f;
        #pragma unroll
        for (int e = 0; e < 16; e++) { float v = Qs[r][part * 16 + e]; s += v * v; }
        s += __shfl_xor_sync(0xffffffffu, s, 1);
        s += __shfl_xor_sync(0xffffffffu, s, 2);
        if (part == 0) qq_s[r] = s;
    }

    const int sty = tid >> 3, stx = tid & 7;    // S map: 2 rows x 4 cols
    const int oty = tid >> 4, otx = tid & 15;   // O map: 4 rows x 4 cols
    float acc[4][4] = {};

    for (int t = 0; t < 16; t++) {
        const int k0 = t * 32;
        __syncthreads();  // prev accumulate done with As/Ss; qq_s ready at t=0

        // load K tile 32x64 (512 float4, 2/thread)
        #pragma unroll
        for (int i = 0; i < 2; i++) {
            int lin = tid + i * 256;
            int r = lin >> 4, c4 = lin & 15;
            float4 v = *(const float4*)(Kg + (size_t)(k0 + r) * UDIM + c4 * 4);
            *(float4*)(&As[r][c4 * 4]) = v;
        }
        __syncthreads();

        // kk norms: rows 32, 4 threads/row (tid < 128)
        if (tid < 128) {
            int r = tid >> 2, part = tid & 3;
            float s = 0.f;
            #pragma unroll
            for (int e = 0; e < 16; e++) { float v = As[r][part * 16 + e]; s += v * v; }
            s += __shfl_xor_sync(0xffffffffu, s, 1);
            s += __shfl_xor_sync(0xffffffffu, s, 2);
            if (part == 0) kk_s[r] = s;
        }
        __syncthreads();

        // S compute: dot[2][4] over d, float4 inner loads
        {
            float dot[2][4] = {};
            #pragma unroll
            for (int d4 = 0; d4 < 16; d4++) {
                float4 qv0 = *(const float4*)(&Qs[sty * 2 + 0][d4 * 4]);
                float4 qv1 = *(const float4*)(&Qs[sty * 2 + 1][d4 * 4]);
                #pragma unroll
                for (int j = 0; j < 4; j++) {
                    float4 av = *(const float4*)(&As[stx * 4 + j][d4 * 4]);
                    dot[0][j] += qv0.x * av.x + qv0.y * av.y + qv0.z * av.z + qv0.w * av.w;
                    dot[1][j] += qv1.x * av.x + qv1.y * av.y + qv1.z * av.z + qv1.w * av.w;
                }
            }
            #pragma unroll
            for (int i = 0; i < 2; i++) {
                int r = sty * 2 + i;
                float qmv = qm_s[r];
                float4 w;
                #pragma unroll
                for (int j = 0; j < 4; j++) {
                    float d2 = fmaxf(qq_s[r] + kk_s[stx * 4 + j] - 2.f * dot[i][j], 1e-12f);
                    float sc = -sqrtf(d2) * 0.125f;       // / sqrt(D)=8
                    Ss[r][stx * 4 + j] = sc;
                    ((float*)&w)[j] = sc * qmv;
                }
                *(float4*)(score_out + ((size_t)(hb * LSEQ + q0 + r)) * LSEQ + k0 + stx * 4) = w;
            }
        }
        __syncthreads();

        // load V tile into As (As is free) + online-softmax pass on Ss
        #pragma unroll
        for (int i = 0; i < 2; i++) {
            int lin = tid + i * 256;
            int r = lin >> 4, c4 = lin & 15;
            float4 v = *(const float4*)(Vg + (size_t)(k0 + r) * UDIM + c4 * 4);
            *(float4*)(&As[r][c4 * 4]) = v;
        }
        {
            int r = tid >> 2, part = tid & 3;
            float vals[8];
            float mx = -3.0e38f;
            #pragma unroll
            for (int e = 0; e < 8; e++) {
                vals[e] = Ss[r][part * 8 + e];
                mx = fmaxf(mx, vals[e]);
            }
            mx = fmaxf(mx, __shfl_xor_sync(0xffffffffu, mx, 1));
            mx = fmaxf(mx, __shfl_xor_sync(0xffffffffu, mx, 2));
            float old_m = m_s[r];
            float new_m = fmaxf(old_m, mx);
            float sum = 0.f;
            #pragma unroll
            for (int e = 0; e < 8; e++) {
                float p = __expf(vals[e] - new_m);
                Ss[r][part * 8 + e] = p;
                sum += p;
            }
            sum += __shfl_xor_sync(0xffffffffu, sum, 1);
            sum += __shfl_xor_sync(0xffffffffu, sum, 2);
            if (part == 0) {
                float fac = __expf(old_m - new_m);
                l_s[r] = l_s[r] * fac + sum;
                m_s[r] = new_m;
                fac_s[r] = fac;
            }
        }
        __syncthreads();

        // accumulate O += P * V  (rescale by fac first)
        {
            #pragma unroll
            for (int i = 0; i < 4; i++) {
                float f = fac_s[oty * 4 + i];
                #pragma unroll
                for (int j = 0; j < 4; j++) acc[i][j] *= f;
            }
            #pragma unroll
            for (int kk = 0; kk < 32; kk++) {
                float4 vv = *(const float4*)(&As[kk][otx * 4]);
                float p[4];
                #pragma unroll
                for (int i = 0; i < 4; i++) p[i] = Ss[oty * 4 + i][kk];  // broadcast
                #pragma unroll
                for (int i = 0; i < 4; i++) {
                    acc[i][0] += p[i] * vv.x;
                    acc[i][1] += p[i] * vv.y;
                    acc[i][2] += p[i] * vv.z;
                    acc[i][3] += p[i] * vv.w;
                }
            }
        }
    }

    // epilogue: out = (acc / l) * qm, merged-head layout
    #pragma unroll
    for (int i = 0; i < 4; i++) {
        int r = oty * 4 + i;
        float scale = qm_s[r] / l_s[r];
        float4 o;
        #pragma unroll
        for (int j = 0; j < 4; j++) ((float*)&o)[j] = acc[i][j] * scale;
        *(float4*)(out + ((size_t)(b * LSEQ + q0 + r)) * UDIM + h * DDIM + otx * 4) = o;
    }
}

// ---------------- launcher ----------------
extern "C" void kernel_launch(void* const* d_in, const int* in_sizes, int n_in,
                              void* d_out, int out_size) {
    (void)in_sizes; (void)n_in; (void)out_size;
    const float* queries = (const float*)d_in[0];
    const float* keys    = (const float*)d_in[1];
    const float* values  = (const float*)d_in[2];
    const float* Wq = (const float*)d_in[3];
    const float* bq = (const float*)d_in[4];
    const float* Wk = (const float*)d_in[5];
    const float* bk = (const float*)d_in[6];
    const float* Wv = (const float*)d_in[7];
    const float* bv = (const float*)d_in[8];

    float* out_ptr   = (float*)d_out;                                   // [B,L,U]
    float* score_ptr = out_ptr + (size_t)BDIM * LSEQ * UDIM;            // [HB,L,L]

    dim3 ggrid(BDIM * LSEQ / 64, UDIM / 64, 3);
    qkv_gemm_kernel<<<ggrid, 256>>>(queries, keys, values, Wq, bq, Wk, bk, Wv, bv);

    qm_kernel<<<(BDIM * LSEQ * 32) / 256, 256>>>(queries);

    dim3 agrid(LSEQ / 64, HBDIM);
    attn_kernel<<<agrid, 256>>>(out_ptr, score_ptr);
}

// round 3
// speedup vs baseline: 1.7326x; 1.7326x over previous
#include <cuda_runtime.h>
#include <cstdint>

#define LSEQ 512
#define UDIM 512
#define BDIM 4
#define HDIM 8
#define DDIM 64
#define HBDIM 32

typedef unsigned long long ull;

// ---------------- scratch (device globals, no allocation) ----------------
__device__ float g_Q[BDIM * LSEQ * UDIM];
__device__ float g_K[BDIM * LSEQ * UDIM];
__device__ float g_V[BDIM * LSEQ * UDIM];
__device__ float g_Wt[3 * UDIM * UDIM];   // W transposed: [z][n][k]
__device__ float g_qm[BDIM * LSEQ];

// ---------------- packed f32x2 + approx helpers ----------------
__device__ __forceinline__ void fma2(ull& d, ull a, ull b) {
    asm("fma.rn.f32x2 %0, %1, %2, %0;" : "+l"(d) : "l"(a), "l"(b));
}
__device__ __forceinline__ ull pk2(float x, float y) {
    ull r; asm("mov.b64 %0, {%1, %2};" : "=l"(r) : "f"(x), "f"(y)); return r;
}
__device__ __forceinline__ float2 upk(ull v) {
    float2 f; asm("mov.b64 {%0, %1}, %2;" : "=f"(f.x), "=f"(f.y) : "l"(v)); return f;
}
__device__ __forceinline__ float hsum(ull v) { float2 f = upk(v); return f.x + f.y; }
__device__ __forceinline__ float sqrt_ap(float x) {
    float r; asm("sqrt.approx.f32 %0, %1;" : "=f"(r) : "f"(x)); return r;
}
__device__ __forceinline__ float ex2_ap(float x) {
    float r; asm("ex2.approx.f32 %0, %1;" : "=f"(r) : "f"(x)); return r;
}

// ---------------- cp.async helpers ----------------
__device__ __forceinline__ void cpa16(void* sdst, const void* gsrc) {
    uint32_t s = (uint32_t)__cvta_generic_to_shared(sdst);
    asm volatile("cp.async.cg.shared.global [%0], [%1], 16;" :: "r"(s), "l"(gsrc));
}
#define CPA_COMMIT() asm volatile("cp.async.commit_group;")
#define CPA_WAIT(n)  asm volatile("cp.async.wait_group %0;" :: "n"(n))

// ---------------- kernel 0: transpose W (3 MB, once) ----------------
__global__ void transpose_w_kernel(const float* __restrict__ Wq,
                                   const float* __restrict__ Wk,
                                   const float* __restrict__ Wv) {
    __shared__ float t[32][33];
    const float* W = (blockIdx.z == 0) ? Wq : (blockIdx.z == 1) ? Wk : Wv;
    float* D = g_Wt + (size_t)blockIdx.z * UDIM * UDIM;
    int k0 = blockIdx.x * 32;
    int n0 = blockIdx.y * 32;
    int tx = threadIdx.x & 31, ty = threadIdx.x >> 5;
    #pragma unroll
    for (int i = 0; i < 4; i++) {
        int r = ty + i * 8;
        t[r][tx] = W[(size_t)(k0 + r) * UDIM + n0 + tx];   // t[a][b]=W[k0+a][n0+b]
    }
    __syncthreads();
    #pragma unroll
    for (int i = 0; i < 4; i++) {
        int r = ty + i * 8;
        D[(size_t)(n0 + r) * UDIM + k0 + tx] = t[tx][r];   // Wt[n][k]=W[k][n]
    }
}

// ---------------- kernel 1: fused GEMM + bias + relu (f32x2 k-pairs) ------
// C[2048x512] = relu(X @ W + b). BM=128, BN=64, BK=16, 128 thr, 8m x 8n/thread.
// Both operands k-contiguous (X natural, Wt transposed) -> natural f32x2 pairs.
// Stride 20 floats (5 chunks, odd) => consecutive phase rows conflict-free.
#define GBM 128
#define GBN 64
#define GBK 16
#define GST 20
#define GXSZ (GBM * GST)
#define GWSZ (GBN * GST)

__global__ __launch_bounds__(128, 2)
void qkv_gemm_kernel(const float* __restrict__ q_in,
                     const float* __restrict__ k_in,
                     const float* __restrict__ v_in,
                     const float* __restrict__ bq,
                     const float* __restrict__ bk,
                     const float* __restrict__ bv) {
    __shared__ float Xs[2][GXSZ];
    __shared__ float Ws[2][GWSZ];

    const float* X; const float* bias; float* dst;
    if (blockIdx.z == 0)      { X = q_in; bias = bq; dst = g_Q; }
    else if (blockIdx.z == 1) { X = k_in; bias = bk; dst = g_K; }
    else                      { X = v_in; bias = bv; dst = g_V; }
    const float* Wt = g_Wt + (size_t)blockIdx.z * UDIM * UDIM;

    const int tid = threadIdx.x;
    const int m0 = blockIdx.x * GBM;
    const int n0 = blockIdx.y * GBN;
    const int ty = tid >> 3;      // 0..15 -> 8 m-rows each (phase-broadcast reads)
    const int tx = tid & 7;       // n-rows {tx + 8j}  (phase rows consecutive)

    auto issue = [&](int t, int buf) {
        // X tile 128x16 = 512 chunks, 4/thread
        #pragma unroll
        for (int i = 0; i < 4; i++) {
            int lin = tid + i * 128;
            int r = lin >> 2, c = lin & 3;
            cpa16(&Xs[buf][r * GST + c * 4], X + (size_t)(m0 + r) * UDIM + t * GBK + c * 4);
        }
        // W tile 64x16 = 256 chunks, 2/thread
        #pragma unroll
        for (int i = 0; i < 2; i++) {
            int lin = tid + i * 128;
            int r = lin >> 2, c = lin & 3;
            cpa16(&Ws[buf][r * GST + c * 4], Wt + (size_t)(n0 + r) * UDIM + t * GBK + c * 4);
        }
        CPA_COMMIT();
    };

    ull acc[8][8] = {};
    issue(0, 0);

    for (int t = 0; t < 32; t++) {
        if (t < 31) { issue(t + 1, (t + 1) & 1); CPA_WAIT(1); }
        else        { CPA_WAIT(0); }
        __syncthreads();

        const float* xb = &Xs[t & 1][ty * 8 * GST];
        const float* wb = &Ws[t & 1][0];
        #pragma unroll
        for (int k4 = 0; k4 < 4; k4++) {
            ulonglong2 w[8];
            #pragma unroll
            for (int j = 0; j < 8; j++)
                w[j] = *(const ulonglong2*)(wb + (tx + 8 * j) * GST + k4 * 4);
            #pragma unroll
            for (int i = 0; i < 8; i++) {
                ulonglong2 a = *(const ulonglong2*)(xb + i * GST + k4 * 4);
                #pragma unroll
                for (int j = 0; j < 8; j++) {
                    fma2(acc[i][j], a.x, w[j].x);
                    fma2(acc[i][j], a.y, w[j].y);
                }
            }
        }
        __syncthreads();
    }

    float bv8[8];
    #pragma unroll
    for (int j = 0; j < 8; j++) bv8[j] = bias[n0 + tx + 8 * j];
    #pragma unroll
    for (int i = 0; i < 8; i++) {
        size_t mrow = (size_t)(m0 + ty * 8 + i) * UDIM;
        #pragma unroll
        for (int j = 0; j < 8; j++) {
            float v = hsum(acc[i][j]) + bv8[j];
            dst[mrow + n0 + tx + 8 * j] = v > 0.f ? v : 0.f;
        }
    }
}

// ---------------- kernel 2: query mask ----------------
__global__ void qm_kernel(const float* __restrict__ q_in) {
    int warp = (blockIdx.x * blockDim.x + threadIdx.x) >> 5;
    int lane = threadIdx.x & 31;
    if (warp >= BDIM * LSEQ) return;
    float s = 0.f;
    for (int e = lane; e < UDIM; e += 32) s += q_in[(size_t)warp * UDIM + e];
    #pragma unroll
    for (int o = 16; o; o >>= 1) s += __shfl_xor_sync(0xffffffffu, s, o);
    if (lane == 0) g_qm[warp] = (s != 0.f) ? 1.f : 0.f;
}

// ---------------- kernel 3: fused euclidean attention ----------------
// Block = 64 q-rows x one hb, 256 thr. 8 k-tiles of 64, 3-buffer K/V rotation.
// Fixed-max softmax (scores <= 0): p = exp(s) directly; l in registers.
// smem floats: Qs 64x64 | KV 3x(64x68) | Ss 64x68
#define A_QST 64
#define A_KST 68
#define A_SST 68
#define AOFF_Q  0
#define AOFF_KV (64 * A_QST)                   // 4096
#define AOFF_SS (AOFF_KV + 3 * 64 * A_KST)     // 4096 + 13056 = 17152
#define ATTN_SMEM_FLOATS (AOFF_SS + 64 * A_SST)  // 21504
#define ATTN_SMEM_BYTES (ATTN_SMEM_FLOATS * 4)   // 86016

__global__ __launch_bounds__(256, 1)
void attn_kernel(float* __restrict__ out, float* __restrict__ score_out) {
    extern __shared__ float smf[];
    float* Qs = smf + AOFF_Q;
    float* KV = smf + AOFF_KV;
    float* Ss = smf + AOFF_SS;

    const int tid = threadIdx.x;
    const int ty = tid >> 4;      // 0..15 -> 4 q-rows each (broadcast reads)
    const int tx = tid & 15;      // k-cols {tx + 16j} (phase rows consecutive)
    const int q0 = blockIdx.x * 64;
    const int hb = blockIdx.y;
    const int h = hb >> 2;        // hb = h*BDIM + b
    const int b = hb & 3;

    const float* Qg = g_Q + ((size_t)(b * LSEQ + q0)) * UDIM + h * DDIM;
    const float* Kg = g_K + ((size_t)(b * LSEQ)) * UDIM + h * DDIM;
    const float* Vg = g_V + ((size_t)(b * LSEQ)) * UDIM + h * DDIM;

    auto load_kv = [&](const float* src, float* dst) {
        #pragma unroll
        for (int i = 0; i < 4; i++) {
            int lin = tid + i * 256;
            int r = lin >> 4, c = lin & 15;
            cpa16(dst + r * A_KST + c * 4, src + (size_t)r * UDIM + c * 4);
        }
    };

    // group 0: Q + K0
    #pragma unroll
    for (int i = 0; i < 4; i++) {
        int lin = tid + i * 256;
        int r = lin >> 4, c = lin & 15;
        cpa16(Qs + r * A_QST + c * 4, Qg + (size_t)r * UDIM + c * 4);
    }
    load_kv(Kg, KV + 0 * 64 * A_KST);
    CPA_COMMIT();                                   // idx 0: Q+K0
    load_kv(Vg, KV + 1 * 64 * A_KST);
    CPA_COMMIT();                                   // idx 1: V0
    load_kv(Kg + (size_t)64 * UDIM, KV + 2 * 64 * A_KST);
    CPA_COMMIT();                                   // idx 2: K1

    float qm_r[4], l_acc[4];
    #pragma unroll
    for (int i = 0; i < 4; i++) {
        qm_r[i] = g_qm[b * LSEQ + q0 + ty * 4 + i];
        l_acc[i] = 0.f;
    }

    CPA_WAIT(2);           // Q+K0 (and V0) done
    __syncthreads();

    // qq norms once (Q reads are phase-broadcasts)
    float qq[4];
    {
        ull qq2[4] = {};
        #pragma unroll
        for (int d4 = 0; d4 < 16; d4++) {
            #pragma unroll
            for (int i = 0; i < 4; i++) {
                ulonglong2 a = *(const ulonglong2*)(Qs + (ty * 4 + i) * A_QST + d4 * 4);
                fma2(qq2[i], a.x, a.x);
                fma2(qq2[i], a.y, a.y);
            }
        }
        #pragma unroll
        for (int i = 0; i < 4; i++) qq[i] = hsum(qq2[i]);
    }

    ull oacc[4][2] = {};     // 4 q-rows x 2 d-pairs (d = tx*4 .. tx*4+3)
    const float LOG2E = 1.4426950408889634f;

    for (int t = 0; t < 8; t++) {
        float* Kb = KV + ((2 * t) % 3) * 64 * A_KST;
        float* Vb = KV + ((2 * t + 1) % 3) * 64 * A_KST;

        // T_t: prefetch K_{t+1} into V_{t-1}'s slot (freed by PV(t-1) + sync)
        if (t >= 1 && t <= 6)
            load_kv(Kg + (size_t)(t + 1) * 64 * UDIM, KV + ((2 * t + 2) % 3) * 64 * A_KST);
        CPA_COMMIT();                               // idx 3+2t
        CPA_WAIT(2);                                // K_t ready
        __syncthreads();

        // ---- S compute: dots + kk norms fused ----
        ull dot[4][4] = {};
        ull kk2[4] = {};
        #pragma unroll
        for (int d4 = 0; d4 < 16; d4++) {
            ulonglong2 kv4[4];
            #pragma unroll
            for (int j = 0; j < 4; j++) {
                kv4[j] = *(const ulonglong2*)(Kb + (tx + 16 * j) * A_KST + d4 * 4);
                fma2(kk2[j], kv4[j].x, kv4[j].x);
                fma2(kk2[j], kv4[j].y, kv4[j].y);
            }
            #pragma unroll
            for (int i = 0; i < 4; i++) {
                ulonglong2 a = *(const ulonglong2*)(Qs + (ty * 4 + i) * A_QST + d4 * 4);
                #pragma unroll
                for (int j = 0; j < 4; j++) {
                    fma2(dot[i][j], a.x, kv4[j].x);
                    fma2(dot[i][j], a.y, kv4[j].y);
                }
            }
        }
        float kk[4];
        #pragma unroll
        for (int j = 0; j < 4; j++) kk[j] = hsum(kk2[j]);

        #pragma unroll
        for (int i = 0; i < 4; i++) {
            int r = ty * 4 + i;
            size_t srow = ((size_t)(hb * LSEQ + q0 + r)) * LSEQ + t * 64;
            #pragma unroll
            for (int j = 0; j < 4; j++) {
                float d2 = fmaxf(qq[i] + kk[j] - 2.f * hsum(dot[i][j]), 1e-12f);
                float s = -sqrt_ap(d2) * 0.125f;
                score_out[srow + tx + 16 * j] = s * qm_r[i];
                float p = ex2_ap(s * LOG2E);
                Ss[r * A_SST + tx + 16 * j] = p;
                l_acc[i] += p;
            }
        }
        __syncthreads();     // Ss ready; Kb fully consumed

        // U_t: prefetch V_{t+1} into K_t's slot
        if (t < 7)
            load_kv(Vg + (size_t)(t + 1) * 64 * UDIM, KV + ((2 * t) % 3) * 64 * A_KST);
        CPA_COMMIT();                               // idx 4+2t
        CPA_WAIT(2);                                // V_t ready
        __syncthreads();

        // ---- PV accumulate: O += P * V ----
        #pragma unroll
        for (int k4 = 0; k4 < 16; k4++) {
            float4 p4[4];
            #pragma unroll
            for (int i = 0; i < 4; i++)
                p4[i] = *(const float4*)(Ss + (ty * 4 + i) * A_SST + k4 * 4);
            #pragma unroll
            for (int kk_ = 0; kk_ < 4; kk_++) {
                ulonglong2 v = *(const ulonglong2*)(Vb + (k4 * 4 + kk_) * A_KST + tx * 4);
                #pragma unroll
                for (int i = 0; i < 4; i++) {
                    float pe = ((const float*)&p4[i])[kk_];
                    ull p2 = pk2(pe, pe);
                    fma2(oacc[i][0], p2, v.x);
                    fma2(oacc[i][1], p2, v.y);
                }
            }
        }
        __syncthreads();     // V_t consumed before next T-load overwrite
    }

    // l reduction across the 16 tx lanes sharing each q-row (butterfly)
    #pragma unroll
    for (int i = 0; i < 4; i++) {
        #pragma unroll
        for (int o = 1; o < 16; o <<= 1)
            l_acc[i] += __shfl_xor_sync(0xffffffffu, l_acc[i], o);
    }

    // epilogue: out = (O / l) * qm, merged-head layout
    #pragma unroll
    for (int i = 0; i < 4; i++) {
        int r = ty * 4 + i;
        float scale = qm_r[i] / l_acc[i];
        float2 f0 = upk(oacc[i][0]);
        float2 f1 = upk(oacc[i][1]);
        float4 o;
        o.x = f0.x * scale; o.y = f0.y * scale;
        o.z = f1.x * scale; o.w = f1.y * scale;
        *(float4*)(out + ((size_t)(b * LSEQ + q0 + r)) * UDIM + h * DDIM + tx * 4) = o;
    }
}

// ---------------- launcher ----------------
extern "C" void kernel_launch(void* const* d_in, const int* in_sizes, int n_in,
                              void* d_out, int out_size) {
    (void)in_sizes; (void)n_in; (void)out_size;
    const float* queries = (const float*)d_in[0];
    const float* keys    = (const float*)d_in[1];
    const float* values  = (const float*)d_in[2];
    const float* Wq = (const float*)d_in[3];
    const float* bq = (const float*)d_in[4];
    const float* Wk = (const float*)d_in[5];
    const float* bk = (const float*)d_in[6];
    const float* Wv = (const float*)d_in[7];
    const float* bv = (const float*)d_in[8];

    float* out_ptr   = (float*)d_out;
    float* score_ptr = out_ptr + (size_t)BDIM * LSEQ * UDIM;

    // opt-in to >48KB dynamic smem for attention (idempotent, capture-safe)
    cudaFuncSetAttribute(attn_kernel, cudaFuncAttributeMaxDynamicSharedMemorySize,
                         ATTN_SMEM_BYTES);

    dim3 tgrid(UDIM / 32, UDIM / 32, 3);
    transpose_w_kernel<<<tgrid, 256>>>(Wq, Wk, Wv);

    dim3 ggrid(BDIM * LSEQ / GBM, UDIM / GBN, 3);
    qkv_gemm_kernel<<<ggrid, 128>>>(queries, keys, values, bq, bk, bv);

    qm_kernel<<<(BDIM * LSEQ * 32) / 256, 256>>>(queries);

    dim3 agrid(LSEQ / 64, HBDIM);
    attn_kernel<<<agrid, 256, ATTN_SMEM_BYTES>>>(out_ptr, score_ptr);
}